// round 5
// baseline (speedup 1.0000x reference)
#include <cuda_runtime.h>
#include <cuda_fp16.h>
#include <cstdint>
#include <cstddef>

#define FD 128
#define NN 25000
#define NE 400000
#define TILE 128
// smem: A 128x136 fp16 (34816 B) + B 128x136 fp16 (34816 B); staging Gst 128x132 f32 overlaps
#define SMEM_BYTES (2 * 128 * 136 * 2)

// ---------------- device scratch (no allocation allowed) --------------------
__device__ float g_P[NN * FD];
__device__ float g_Q[NN * FD];
__device__ float g_eps[NN];
__device__ float g_as[NE];          // edge logits, CSR order
__device__ __half g_m[NE * FD];     // h_src ⊙ gh, fp16, CSR order
__device__ __half g_W[4][FD * FD];  // [Wt,Wm,Wb,We1] stored [n*FD+k]
__device__ int g_deg[NN];           // invariant: zero at launch entry (restored by k_agg)
__device__ int g_off[NN];
__device__ int g_end[NN];
__device__ int g_cur[NN];
__device__ int g_pos[NE];
__device__ int g_cursor;            // invariant: zero at launch entry (restored by k_agg)

// ---------------- helpers ----------------------------------------------------
__device__ __forceinline__ uint32_t smem_u32(const void* p) {
    uint32_t a;
    asm("{ .reg .u64 t; cvta.to.shared.u64 t, %1; cvt.u32.u64 %0, t; }" : "=r"(a) : "l"(p));
    return a;
}
__device__ __forceinline__ void ldsm4(uint32_t r[4], uint32_t addr) {
    asm volatile("ldmatrix.sync.aligned.m8n8.x4.shared.b16 {%0,%1,%2,%3}, [%4];"
                 : "=r"(r[0]), "=r"(r[1]), "=r"(r[2]), "=r"(r[3])
                 : "r"(addr));
}
__device__ __forceinline__ void mma16816(float c[4], const uint32_t a[4], uint32_t b0,
                                         uint32_t b1) {
    asm volatile(
        "mma.sync.aligned.m16n8k16.row.col.f32.f16.f16.f32 "
        "{%0,%1,%2,%3},{%4,%5,%6,%7},{%8,%9},{%0,%1,%2,%3};"
        : "+f"(c[0]), "+f"(c[1]), "+f"(c[2]), "+f"(c[3])
        : "r"(a[0]), "r"(a[1]), "r"(a[2]), "r"(a[3]), "r"(b0), "r"(b1));
}
__device__ __forceinline__ uint32_t pack_h2(float x, float y) {
    __half2 h = __floats2half2_rn(x, y);
    return *reinterpret_cast<uint32_t*>(&h);
}

// ---------------- prep: weight convert + degree histogram -------------------
__global__ void k_prep(const float* __restrict__ Wa1, const float* __restrict__ We1,
                       const int* __restrict__ dst) {
    int tid = blockIdx.x * blockDim.x + threadIdx.x;
    if (tid < NE) atomicAdd(&g_deg[dst[tid]], 1);
    if (tid < 4 * FD * FD) {
        int m = tid >> 14;
        int r = tid & (FD * FD - 1);
        int n = r >> 7;
        int k = r & 127;
        float w = (m < 3) ? Wa1[(m * FD + k) * FD + n] : We1[k * FD + n];
        g_W[m][n * FD + k] = __float2half(w);
    }
}

// ---------------- GEMM building blocks (256 threads, C tile 128x128) --------
__device__ __forceinline__ void load_A(const float* __restrict__ src, int row0, int maxrow,
                                       char* smem) {
    int t = threadIdx.x;
#pragma unroll
    for (int it = 0; it < 16; it++) {
        int linear = it * 256 + t;
        int r = linear >> 5;
        int c = (linear & 31) * 4;
        float4 v = make_float4(0.f, 0.f, 0.f, 0.f);
        if (row0 + r < maxrow)
            v = *reinterpret_cast<const float4*>(src + (size_t)(row0 + r) * FD + c);
        uint2 pk;
        pk.x = pack_h2(v.x, v.y);
        pk.y = pack_h2(v.z, v.w);
        *reinterpret_cast<uint2*>(smem + r * 272 + c * 2) = pk;
    }
}
__device__ __forceinline__ void load_B(const __half* __restrict__ w, char* smem) {
    const uint32_t* s4 = reinterpret_cast<const uint32_t*>(w);
    int t = threadIdx.x;
    char* sB = smem + 34816;
#pragma unroll
    for (int it = 0; it < 32; it++) {
        int linear = it * 256 + t;
        int n = linear >> 6;
        int kk = linear & 63;
        *reinterpret_cast<uint32_t*>(sB + n * 272 + kk * 4) = s4[linear];
    }
}

// warp grid 4(M) x 2(N); warp tile 32x64; per-thread C[2][8][4]
__device__ __forceinline__ void mainloop(char* smem, float C[2][8][4]) {
    int lane = threadIdx.x & 31;
    int wid = threadIdx.x >> 5;
    int wm = wid >> 1, wn = wid & 1;
    uint32_t sA = smem_u32(smem);
    uint32_t sB = sA + 34816;
    uint32_t aA0 = sA + (wm * 32 + (lane & 15)) * 272 + (lane >> 4) * 16;
    uint32_t aA1 = aA0 + 16 * 272;
    uint32_t aB[4];
#pragma unroll
    for (int p = 0; p < 4; p++)
        aB[p] = sB + (wn * 64 + p * 16 + (lane & 7) + ((lane >> 4) & 1) * 8) * 272 +
                ((lane >> 3) & 1) * 16;
#pragma unroll
    for (int ks = 0; ks < 8; ks++) {
        uint32_t A0[4], A1[4], Bf[4][4];
        ldsm4(A0, aA0 + ks * 32);
        ldsm4(A1, aA1 + ks * 32);
#pragma unroll
        for (int p = 0; p < 4; p++) ldsm4(Bf[p], aB[p] + ks * 32);
#pragma unroll
        for (int p = 0; p < 4; p++) {
            mma16816(C[0][2 * p], A0, Bf[p][0], Bf[p][1]);
            mma16816(C[1][2 * p], A1, Bf[p][0], Bf[p][1]);
            mma16816(C[0][2 * p + 1], A0, Bf[p][2], Bf[p][3]);
            mma16816(C[1][2 * p + 1], A1, Bf[p][2], Bf[p][3]);
        }
    }
}

__device__ __forceinline__ void zero_C(float C[2][8][4]) {
#pragma unroll
    for (int a = 0; a < 2; a++)
#pragma unroll
        for (int b = 0; b < 8; b++)
#pragma unroll
            for (int c = 0; c < 4; c++) C[a][b][c] = 0.f;
}

__device__ __forceinline__ void stage_C(float C[2][8][4], float* Gst) {
    int lane = threadIdx.x & 31;
    int wid = threadIdx.x >> 5;
    int wm = wid >> 1, wn = wid & 1, g = lane >> 2, q = lane & 3;
#pragma unroll
    for (int mt = 0; mt < 2; mt++)
#pragma unroll
        for (int nt = 0; nt < 8; nt++) {
            int row = wm * 32 + mt * 16 + g;
            int col = wn * 64 + nt * 8 + q * 2;
            *reinterpret_cast<float2*>(Gst + row * 132 + col) = make_float2(C[mt][nt][0], C[mt][nt][1]);
            *reinterpret_cast<float2*>(Gst + (row + 8) * 132 + col) = make_float2(C[mt][nt][2], C[mt][nt][3]);
        }
}

// ---------------- edge kernel: logits + fp16 message write (CSR order) ------
__global__ void __launch_bounds__(256, 2)
k_edge(const float* __restrict__ gh, const float* __restrict__ nf, const int* __restrict__ src,
       const int* __restrict__ dst, const float* __restrict__ ba1, const float* __restrict__ Wa2,
       const float* __restrict__ ba2) {
    extern __shared__ char smem[];
    int m0 = blockIdx.x * TILE;
    int lane = threadIdx.x & 31;
    int wid = threadIdx.x >> 5;
    int half = lane >> 4;
    int r = wid * 16 + (lane & 15);
    int e = m0 + r;
    int es = src[e], ed = dst[e];
    int pos = g_pos[e];

    load_A(gh, m0, NE, smem);
    load_B(g_W[2], smem);
    __syncthreads();

    float C[2][8][4];
    zero_C(C);
    mainloop(smem, C);
    __syncthreads();
    float* Gst = reinterpret_cast<float*>(smem);
    stage_C(C, Gst);
    __syncthreads();

    float acc = 0.f;
    const float4* Gp = reinterpret_cast<const float4*>(Gst + r * 132 + half * 64);
    const float4* Pp = reinterpret_cast<const float4*>(g_P + (size_t)es * FD + half * 64);
    const float4* Qp = reinterpret_cast<const float4*>(g_Q + (size_t)ed * FD + half * 64);
    const float4* Bp = reinterpret_cast<const float4*>(ba1 + half * 64);
    const float4* Wp = reinterpret_cast<const float4*>(Wa2 + half * 64);
#pragma unroll
    for (int j = 0; j < 16; j++) {
        float4 gv = Gp[j], pv = Pp[j], qv = Qp[j], bv = Bp[j], wv = Wp[j];
        acc += fmaxf(gv.x + pv.x + qv.x + bv.x, 0.f) * wv.x;
        acc += fmaxf(gv.y + pv.y + qv.y + bv.y, 0.f) * wv.y;
        acc += fmaxf(gv.z + pv.z + qv.z + bv.z, 0.f) * wv.z;
        acc += fmaxf(gv.w + pv.w + qv.w + bv.w, 0.f) * wv.w;
    }
    acc += __shfl_xor_sync(0xffffffffu, acc, 16);
    if (half == 0) g_as[pos] = acc + ba2[0];

    // m[e] = h_src * gh  ->  fp16 at CSR position (coalesced 256B per edge)
    const float4* gh4 = reinterpret_cast<const float4*>(gh);
    const float4* nf4 = reinterpret_cast<const float4*>(nf);
#pragma unroll 1
    for (int t = 0; t < 16; t++) {
        int es_t = __shfl_sync(0xffffffffu, es, t);
        int pos_t = __shfl_sync(0xffffffffu, pos, t);
        int e_t = m0 + wid * 16 + t;
        float4 h = nf4[(size_t)es_t * 32 + lane];
        float4 g = gh4[(size_t)e_t * 32 + lane];
        uint2 pk;
        pk.x = pack_h2(h.x * g.x, h.y * g.y);
        pk.y = pack_h2(h.z * g.z, h.w * g.w);
        *reinterpret_cast<uint2*>(g_m + (size_t)pos_t * FD + lane * 4) = pk;
    }
}

// ---------------- node kernel: P = nf@Wt, Q = nf@Wm, eps --------------------
__global__ void __launch_bounds__(256, 2)
k_node(const float* __restrict__ nf, const float* __restrict__ be1, const float* __restrict__ We2,
       const float* __restrict__ be2) {
    extern __shared__ char smem[];
    int m0 = blockIdx.x * TILE;
    load_A(nf, m0, NN, smem);

    int lane = threadIdx.x & 31;
    int wid = threadIdx.x >> 5;
    int wm = wid >> 1, wn = wid & 1, g = lane >> 2, q = lane & 3;

    const int wsel[3] = {0, 1, 3};
#pragma unroll 1
    for (int it = 0; it < 3; it++) {
        __syncthreads();
        load_B(g_W[wsel[it]], smem);
        __syncthreads();
        float C[2][8][4];
        zero_C(C);
        mainloop(smem, C);

        if (it < 2) {
            float* dstbuf = (it == 0) ? g_P : g_Q;
#pragma unroll
            for (int mt = 0; mt < 2; mt++)
#pragma unroll
                for (int nt = 0; nt < 8; nt++) {
                    int row = m0 + wm * 32 + mt * 16 + g;
                    int col = wn * 64 + nt * 8 + q * 2;
                    if (row < NN)
                        *reinterpret_cast<float2*>(dstbuf + (size_t)row * FD + col) =
                            make_float2(C[mt][nt][0], C[mt][nt][1]);
                    if (row + 8 < NN)
                        *reinterpret_cast<float2*>(dstbuf + (size_t)(row + 8) * FD + col) =
                            make_float2(C[mt][nt][2], C[mt][nt][3]);
                }
        } else {
            __syncthreads();
            float* Gst = reinterpret_cast<float*>(smem);
            stage_C(C, Gst);
            __syncthreads();
            int half = lane >> 4;
            int r = wid * 16 + (lane & 15);
            int node = m0 + r;
            float acc = 0.f;
            const float4* Gp = reinterpret_cast<const float4*>(Gst + r * 132 + half * 64);
            const float4* Bp = reinterpret_cast<const float4*>(be1 + half * 64);
            const float4* Wp = reinterpret_cast<const float4*>(We2 + half * 64);
#pragma unroll
            for (int j = 0; j < 16; j++) {
                float4 gv = Gp[j], bv = Bp[j], wv = Wp[j];
                acc += fmaxf(gv.x + bv.x, 0.f) * wv.x;
                acc += fmaxf(gv.y + bv.y, 0.f) * wv.y;
                acc += fmaxf(gv.z + bv.z, 0.f) * wv.z;
                acc += fmaxf(gv.w + bv.w, 0.f) * wv.w;
            }
            acc += __shfl_xor_sync(0xffffffffu, acc, 16);
            if (half == 0 && node < NN) g_eps[node] = acc + be2[0];
        }
    }
}

// ---------------- parallel range assignment (order-free CSR) ----------------
__global__ void k_scan_fast() {
    __shared__ int wsum[8];
    __shared__ int sbase;
    int n = blockIdx.x * 256 + threadIdx.x;
    int lane = threadIdx.x & 31, w = threadIdx.x >> 5;
    int v = (n < NN) ? g_deg[n] : 0;
    int x = v;
#pragma unroll
    for (int d = 1; d < 32; d <<= 1) {
        int t = __shfl_up_sync(0xffffffffu, x, d);
        if (lane >= d) x += t;
    }
    if (lane == 31) wsum[w] = x;
    __syncthreads();
    if (threadIdx.x == 0) {
        int run = 0;
#pragma unroll
        for (int i = 0; i < 8; i++) {
            int t = wsum[i];
            wsum[i] = run;
            run += t;
        }
        sbase = atomicAdd(&g_cursor, run);
    }
    __syncthreads();
    int off = sbase + wsum[w] + x - v;
    if (n < NN) {
        g_off[n] = off;
        g_cur[n] = off;
        g_end[n] = off + v;
    }
}

// ---------------- scatter: edge -> CSR position -----------------------------
__global__ void k_scatter(const int* __restrict__ dst) {
    int e = blockIdx.x * blockDim.x + threadIdx.x;
    if (e < NE) g_pos[e] = atomicAdd(&g_cur[dst[e]], 1);
}

// ---------------- fused softmax + aggregation: warp per node, all streaming -
__global__ void k_agg(const float* __restrict__ nf, float* __restrict__ out) {
    // restore launch invariants for the next graph replay (g_deg unused after scan)
    int z = blockIdx.x * blockDim.x + threadIdx.x;
    if (z < NN) g_deg[z] = 0;
    if (z == 0) g_cursor = 0;

    int node = z >> 5;
    int lane = threadIdx.x & 31;
    if (node >= NN) return;
    int beg = g_off[node], end = g_end[node];

    // pass 1: max + denom over contiguous logits
    float m = -INFINITY;
    for (int i = beg + lane; i < end; i += 32) m = fmaxf(m, g_as[i]);
#pragma unroll
    for (int d = 16; d; d >>= 1) m = fmaxf(m, __shfl_xor_sync(0xffffffffu, m, d));
    float s = 0.f;
    for (int i = beg + lane; i < end; i += 32) s += __expf(g_as[i] - m);
#pragma unroll
    for (int d = 16; d; d >>= 1) s += __shfl_xor_sync(0xffffffffu, s, d);
    float inv = (s > 0.f) ? 1.f / s : 0.f;

    // pass 2: weighted sum of contiguous fp16 messages (256B per edge, coalesced)
    float4 hv = make_float4(0.f, 0.f, 0.f, 0.f);
#pragma unroll 2
    for (int i = beg; i < end; i++) {
        float w = __expf(g_as[i] - m) * inv;  // broadcast load
        uint2 pk = *reinterpret_cast<const uint2*>(g_m + (size_t)i * FD + lane * 4);
        float2 v0 = __half22float2(*reinterpret_cast<__half2*>(&pk.x));
        float2 v1 = __half22float2(*reinterpret_cast<__half2*>(&pk.y));
        hv.x += w * v0.x;
        hv.y += w * v0.y;
        hv.z += w * v1.x;
        hv.w += w * v1.y;
    }
    float ep = 1.f + g_eps[node];
    const float4* nf4 = reinterpret_cast<const float4*>(nf);
    float4 base = nf4[(size_t)node * 32 + lane];
    float4 r;
    r.x = ep * hv.x + base.x;
    r.y = ep * hv.y + base.y;
    r.z = ep * hv.z + base.z;
    r.w = ep * hv.w + base.w;
    reinterpret_cast<float4*>(out)[(size_t)node * 32 + lane] = r;
}

// ---------------- launch -----------------------------------------------------
extern "C" void kernel_launch(void* const* d_in, const int* in_sizes, int n_in,
                              void* d_out, int out_size) {
    const float* nf = (const float*)d_in[0];
    const float* gh = (const float*)d_in[1];
    const int* src = (const int*)d_in[2];
    const int* dst = (const int*)d_in[3];
    const float* Wa1 = (const float*)d_in[4];
    const float* ba1 = (const float*)d_in[5];
    const float* Wa2 = (const float*)d_in[6];
    const float* ba2 = (const float*)d_in[7];
    const float* We1 = (const float*)d_in[8];
    const float* be1 = (const float*)d_in[9];
    const float* We2 = (const float*)d_in[10];
    const float* be2 = (const float*)d_in[11];
    float* out = (float*)d_out;

    cudaFuncSetAttribute(k_node, cudaFuncAttributeMaxDynamicSharedMemorySize, SMEM_BYTES);
    cudaFuncSetAttribute(k_edge, cudaFuncAttributeMaxDynamicSharedMemorySize, SMEM_BYTES);

    k_prep<<<(NE + 255) / 256, 256>>>(Wa1, We1, dst);
    k_scan_fast<<<(NN + 255) / 256, 256>>>();
    k_scatter<<<(NE + 255) / 256, 256>>>(dst);
    k_node<<<(NN + TILE - 1) / TILE, 256, SMEM_BYTES>>>(nf, be1, We2, be2);
    k_edge<<<NE / TILE, 256, SMEM_BYTES>>>(gh, nf, src, dst, ba1, Wa2, ba2);
    k_agg<<<(NN * 32 + 255) / 256, 256>>>(nf, out);
}